// round 11
// baseline (speedup 1.0000x reference)
#include <cuda_runtime.h>
#include <math.h>

// Problem constants (fixed shapes per reference)
#define NN   32768      // nodes
#define KIN  64         // C_in
#define HC   256        // H*C
#define NH   4          // heads
#define NC   64         // C per head
#define NR   16         // ratio
#define NB   32         // graphs
#define NT   512        // NB*NR targets
#define BM   32         // nodes per CTA
#define NCTA (NN/BM)    // 1024
#define NFIN 16         // finalizer CTAs

// smem float offsets (total 13584 floats = 54336 B -> 4 CTAs/SM)
#define OF_XLS 0        // [32][272]
#define OF_EXS 8704     // [32][68]
#define OF_ATT 10880    // [4][68]
#define OF_XS  11152    // [64][36]
#define OF_DXL 13456    // [32][4]
#define SMEM1  54336

typedef unsigned long long ull;

// ---- packed f32x2 helpers (FFMA2 path; only reachable via PTX) ----
#define FMA2(d, a, b, c) asm("fma.rn.f32x2 %0, %1, %2, %3;" : "=l"(d) : "l"(a), "l"(b), "l"(c))
#define ADD2(d, a, b)    asm("add.rn.f32x2 %0, %1, %2;" : "=l"(d) : "l"(a), "l"(b))
#define ABS2(d, a)       asm("and.b64 %0, %1, 0x7FFFFFFF7FFFFFFF;" : "=l"(d) : "l"(a))
#define PACK2(d, lo, hi) asm("mov.b64 %0, {%1, %2};" : "=l"(d) : "r"(lo), "r"(hi))

__device__ __forceinline__ ull pack_dup(float v) {
    ull d; unsigned u = __float_as_uint(v); PACK2(d, u, u); return d;
}
__device__ __forceinline__ float2 as_f2(ull v) {
    float2 r; unsigned lo = (unsigned)v, hi = (unsigned)(v >> 32);
    r.x = __uint_as_float(lo); r.y = __uint_as_float(hi); return r;
}
__device__ __forceinline__ ull as_u64(float lo, float hi) {
    ull d; PACK2(d, __float_as_uint(lo), __float_as_uint(hi)); return d;
}

// ---- scratch (static device globals; no allocation) ----
// g_den / g_num start zero (.bss) and are RE-ZEROED by the finalizer CTAs of
// each run for the next run. g_cnt is a monotone arrival counter (never reset).
__device__ float g_xrL[64 * 64];       // [c>>2][rh][c&3]  (coalesced for logit)
__device__ float g_dxr[64];            // [rh] = sum_c xr*att
__device__ float g_den[NB * 64];       // per (g, rh)
__device__ float g_num[NT * NH * NC];  // [t][h][c]
__device__ unsigned g_cnt;

// ---------------------------------------------------------------------------
// K0: x_r = xcent_base @ W_r + b_r  (interleaved layout) + dxr reduction
// ---------------------------------------------------------------------------
__global__ void __launch_bounds__(256)
k0_xr(const float* __restrict__ xcb, const float* __restrict__ Wr,
      const float* __restrict__ br, const float* __restrict__ att) {
    __shared__ float xc[KIN];
    __shared__ float va[256];
    int r = blockIdx.x;
    int o = threadIdx.x;               // output column of W_r
    if (o < KIN) xc[o] = xcb[r * KIN + o];
    __syncthreads();

    float s[4] = {0.f, 0.f, 0.f, 0.f};
    #pragma unroll
    for (int kb = 0; kb < KIN; kb += 16) {
        float w[16];
        #pragma unroll
        for (int j = 0; j < 16; j++) w[j] = __ldg(Wr + (kb + j) * HC + o);
        #pragma unroll
        for (int j = 0; j < 16; j++) s[j & 3] = fmaf(xc[kb + j], w[j], s[j & 3]);
    }
    int h = o >> 6, c = o & 63;
    int rh = r * 4 + h;
    float val = br[o] + ((s[0] + s[1]) + (s[2] + s[3]));
    g_xrL[((c >> 2) * 64 + rh) * 4 + (c & 3)] = val;
    va[o] = val * att[o];              // att flat [h*64+c] == o
    __syncthreads();
    if (o < 4) {
        float d = 0.f;
        #pragma unroll 8
        for (int j = 0; j < 64; j++) d += va[o * 64 + j];
        g_dxr[r * 4 + o] = d;
    }
}

// ---------------------------------------------------------------------------
// K1 (fused): per 32-node tile, 4 CTAs/SM
//   phase1: GEMM x@W_l+b_l; B from GLOBAL in k=2 register chunks
//   phase1b: dxl[n][h] = sum_c xl*att  (tiny, 128 threads)
//   phase2: logit = 0.6*(dxl+dxr) + 0.4*sum|z|a; expf; den red.f32
//   phase3: numerator accumulation -> red.v4 to g_num
//   phase4: last 16 CTAs finalize output + re-zero accumulators
// ---------------------------------------------------------------------------
__global__ void __launch_bounds__(256, 4)
k1_main(const float* __restrict__ x, const float* __restrict__ Wl,
        const float* __restrict__ bl, const float* __restrict__ att,
        const int* __restrict__ batch, const float* __restrict__ bias,
        float* __restrict__ out, int out_size) {
    extern __shared__ float sm[];
    float* xls  = sm + OF_XLS;         // [n][h*68+c] stride 272
    float* exs  = sm + OF_EXS;         // [n][h*16+r] stride 68
    float* atts = sm + OF_ATT;         // [h*68+c]
    float* xs   = sm + OF_XS;          // [k][n] stride 36
    float* dxl  = sm + OF_DXL;         // [n][h]

    int tid = threadIdx.x;
    int nb0 = blockIdx.x * BM;
    int g = batch[nb0];

    // --- fill: x tile transposed to xs[k][n] ---
    {
        int n  = tid >> 3;             // 0..31
        int kq = (tid & 7) * 8;
        float4 v0 = *(const float4*)(x + (nb0 + n) * KIN + kq);
        float4 v1 = *(const float4*)(x + (nb0 + n) * KIN + kq + 4);
        xs[(kq + 0) * 36 + n] = v0.x; xs[(kq + 1) * 36 + n] = v0.y;
        xs[(kq + 2) * 36 + n] = v0.z; xs[(kq + 3) * 36 + n] = v0.w;
        xs[(kq + 4) * 36 + n] = v1.x; xs[(kq + 5) * 36 + n] = v1.y;
        xs[(kq + 6) * 36 + n] = v1.z; xs[(kq + 7) * 36 + n] = v1.w;
    }
    // --- fill: att -> atts ---
    {
        int h = tid >> 6, c = tid & 63;
        atts[h * 68 + c] = att[tid];
    }
    __syncthreads();

    // --- GEMM (packed f32x2): thread (tn 0..3, to 0..63)
    //     nodes tn*8..tn*8+7; cols to*4..to*4+3. B from global, kc=2 chunks
    //     (coalesced 512B/warp LDG.128). a-loads warp-uniform broadcast. ---
    int to = tid & 63, tn = tid >> 6;

    ull acc2[8][2];      // [node i][col pair]  (32 regs)
    #pragma unroll
    for (int i = 0; i < 8; i++) { acc2[i][0] = 0ull; acc2[i][1] = 0ull; }

    const float4* wp4 = (const float4*)(Wl + to * 4);   // +k*64 float4s per row
    #pragma unroll 4
    for (int kb = 0; kb < 64; kb += 2) {
        float4 w0 = __ldg(wp4 + kb * 64);
        float4 w1 = __ldg(wp4 + (kb + 1) * 64);
        ull b2[2][2];
        b2[0][0] = as_u64(w0.x, w0.y); b2[0][1] = as_u64(w0.z, w0.w);
        b2[1][0] = as_u64(w1.x, w1.y); b2[1][1] = as_u64(w1.z, w1.w);
        #pragma unroll
        for (int j = 0; j < 2; j++) {
            float4 a0 = *(const float4*)(xs + (kb + j) * 36 + tn * 8);      // bcast
            float4 a1 = *(const float4*)(xs + (kb + j) * 36 + tn * 8 + 4);  // bcast
            ull ad[8];
            ad[0] = pack_dup(a0.x); ad[1] = pack_dup(a0.y);
            ad[2] = pack_dup(a0.z); ad[3] = pack_dup(a0.w);
            ad[4] = pack_dup(a1.x); ad[5] = pack_dup(a1.y);
            ad[6] = pack_dup(a1.z); ad[7] = pack_dup(a1.w);
            #pragma unroll
            for (int i = 0; i < 8; i++) {
                FMA2(acc2[i][0], ad[i], b2[j][0], acc2[i][0]);
                FMA2(acc2[i][1], ad[i], b2[j][1], acc2[i][1]);
            }
        }
    }

    // --- epilogue: add bias (packed), store to SMEM xls [n][h*68+c] ---
    {
        int h = to >> 4;               // head of this column quad
        int c = (to & 15) * 4;
        float4 bv = __ldg((const float4*)(bl + to * 4));
        ull blo = as_u64(bv.x, bv.y), bhi = as_u64(bv.z, bv.w);
        #pragma unroll
        for (int i = 0; i < 8; i++) {
            int n = tn * 8 + i;
            ull v0, v1;
            ADD2(v0, acc2[i][0], blo);
            ADD2(v1, acc2[i][1], bhi);
            ulonglong2 st; st.x = v0; st.y = v1;
            *(ulonglong2*)(xls + n * 272 + h * 68 + c) = st;
        }
    }
    __syncthreads();

    // --- phase1b: dxl[n][h] = sum_c xl*att (128 threads, conflict-free) ---
    if (tid < 128) {
        int n = tid >> 2, h = tid & 3;
        ull a2 = 0ull;
        #pragma unroll
        for (int j = 0; j < 16; j++) {
            ulonglong2 xl = *(const ulonglong2*)(xls + n * 272 + h * 68 + j * 4);
            ulonglong2 at = *(const ulonglong2*)(atts + h * 68 + j * 4);
            FMA2(a2, xl.x, at.x, a2);
            FMA2(a2, xl.y, at.y, a2);
        }
        float2 f = as_f2(a2);
        dxl[n * 4 + h] = f.x + f.y;
    }
    __syncthreads();

    // --- logit + exp, q-tiled: s = 0.6*(dxl+dxr) + 0.4*sum|z|a; den folded ---
    {
        int rh = tid & 63;   // r*4+h
        int nl = tid >> 6;   // 0..3
        int hh = rh & 3;
        int rr = rh >> 2;
        float dxr = __ldg(g_dxr + rh);

        ull s2[8];
        #pragma unroll
        for (int i = 0; i < 8; i++) s2[i] = 0ull;

        #pragma unroll
        for (int qt = 0; qt < 4; qt++) {
            ull at2[8], xr2[8];
            #pragma unroll
            for (int j = 0; j < 4; j++) {
                ulonglong2 t = *(const ulonglong2*)(atts + hh * 68 + qt * 16 + j * 4);
                at2[2 * j] = t.x; at2[2 * j + 1] = t.y;
                // coalesced: lanes rh 0..31 -> consecutive 16B
                float4 u = __ldg((const float4*)(g_xrL + ((qt * 4 + j) * 64 + rh) * 4));
                xr2[2 * j] = as_u64(u.x, u.y); xr2[2 * j + 1] = as_u64(u.z, u.w);
            }
            #pragma unroll
            for (int i = 0; i < 8; i++) {
                int n = nl + 4 * i;
                #pragma unroll
                for (int j = 0; j < 4; j++) {
                    ulonglong2 xl = *(const ulonglong2*)(xls + n * 272 + hh * 68 + qt * 16 + j * 4);
                    ull z, az;
                    ADD2(z, xl.x, xr2[2 * j]);
                    ABS2(az, z);
                    FMA2(s2[i], az, at2[2 * j], s2[i]);
                    ADD2(z, xl.y, xr2[2 * j + 1]);
                    ABS2(az, z);
                    FMA2(s2[i], az, at2[2 * j + 1], s2[i]);
                }
            }
        }

        float den_part = 0.f;
        #pragma unroll
        for (int i = 0; i < 8; i++) {
            int n = nl + 4 * i;
            float2 f2v = as_f2(s2[i]);
            float logit = 0.6f * (dxl[n * 4 + hh] + dxr) + 0.4f * (f2v.x + f2v.y);
            // no max subtraction: logits are O(+-10), exp is safe in fp32
            float e = __expf(logit);
            exs[n * 68 + hh * 16 + rr] = e;
            den_part += e;
        }
        asm volatile("red.global.add.f32 [%0], %1;"
                     :: "l"(g_den + g * 64 + rh), "f"(den_part) : "memory");
    }
    __syncthreads();

    // --- numerator accumulation (packed): thread = (rp, h, cq) ---
    {
        int rp = tid >> 6;          // r-quad: r = rp*4..rp*4+3
        int h  = (tid >> 4) & 3;
        int cq = tid & 15;          // c = cq*4..cq*4+3

        ull a2[4][2];
        #pragma unroll
        for (int r = 0; r < 4; r++) { a2[r][0] = 0ull; a2[r][1] = 0ull; }

        #pragma unroll 4
        for (int n = 0; n < BM; n++) {
            float4 e = *(const float4*)(exs + n * 68 + h * 16 + rp * 4);
            ulonglong2 v = *(const ulonglong2*)(xls + n * 272 + h * 68 + cq * 4);
            ull e0 = pack_dup(e.x), e1 = pack_dup(e.y);
            ull e2 = pack_dup(e.z), e3 = pack_dup(e.w);
            FMA2(a2[0][0], e0, v.x, a2[0][0]); FMA2(a2[0][1], e0, v.y, a2[0][1]);
            FMA2(a2[1][0], e1, v.x, a2[1][0]); FMA2(a2[1][1], e1, v.y, a2[1][1]);
            FMA2(a2[2][0], e2, v.x, a2[2][0]); FMA2(a2[2][1], e2, v.y, a2[2][1]);
            FMA2(a2[3][0], e3, v.x, a2[3][0]); FMA2(a2[3][1], e3, v.y, a2[3][1]);
        }
        float* base = g_num + ((g * NR + rp * 4) * NH + h) * NC + cq * 4;
        #pragma unroll
        for (int r = 0; r < 4; r++) {
            float2 lo = as_f2(a2[r][0]), hi = as_f2(a2[r][1]);
            asm volatile("red.global.add.v4.f32 [%0], {%1,%2,%3,%4};"
                         :: "l"(base + r * NH * NC),
                            "f"(lo.x), "f"(lo.y), "f"(hi.x), "f"(hi.y) : "memory");
        }
    }

    // --- phase4: arrival ticket; last NFIN CTAs finalize + re-zero ---
    __shared__ unsigned s_tk;
    __threadfence();                 // release my reds (every thread)
    __syncthreads();
    if (tid == 0) s_tk = atomicAdd(&g_cnt, 1u);
    __syncthreads();
    unsigned tk  = s_tk;
    unsigned pos = tk & (NCTA - 1);  // position within this run (NCTA power of 2)
    if (pos < NCTA - NFIN) return;

    unsigned run_base = tk - pos;
    if (tid == 0) {
        // wrap-safe monotone wait: all NCTA CTAs of this run have arrived
        while (*((volatile unsigned*)&g_cnt) - run_base < NCTA) { }
    }
    __syncthreads();
    __threadfence();                 // acquire: all reds visible

    int slice = (int)(pos - (NCTA - NFIN));   // 0..15
    int t0 = slice * (NT / NFIN);             // 32 t's per slice

    // reciprocal of den for my t-range: 2 graphs x 64 rh = 128 values -> smem
    float* rden = sm;                         // reuse smem
    if (tid < 128) {
        int gg = 2 * slice + (tid >> 6);
        rden[tid] = 1.0f / g_den[gg * 64 + (tid & 63)];
    }
    __syncthreads();

    // outputs: 32 t x 64 c = 2048 values
    for (int i = tid; i < (NT / NFIN) * NC; i += 256) {
        int t = t0 + (i >> 6), c = i & 63;
        int lg = (t >> 4) - 2 * slice;        // 0 or 1
        int r  = t & 15;
        float s = 0.f;
        #pragma unroll
        for (int h = 0; h < NH; h++)
            s += g_num[(t * NH + h) * NC + c] * rden[lg * 64 + r * 4 + h];
        out[t * NC + c] = 0.25f * s + bias[c];
    }
    // batchcent tail
    {
        int j = t0 + tid;                     // 32 entries per slice
        if (tid < NT / NFIN && NT * NC + j < out_size)
            out[NT * NC + j] = (float)(j >> 4);
    }
    __syncthreads();                          // reads done before re-zero

    // re-zero my disjoint slices for the next run
    {
        float4 z4 = {0.f, 0.f, 0.f, 0.f};
        float* nb = g_num + t0 * NH * NC;     // 32*256 = 8192 floats
        for (int i = tid * 4; i < (NT / NFIN) * NH * NC; i += 1024)
            *(float4*)(nb + i) = z4;
        if (tid < 32)
            *(float4*)(g_den + slice * 128 + tid * 4) = z4;
    }
}

// ---------------------------------------------------------------------------
extern "C" void kernel_launch(void* const* d_in, const int* in_sizes, int n_in,
                              void* d_out, int out_size) {
    const float* x    = (const float*)d_in[0];
    // d_in[1] = edge_index (unused by forward)
    const int*   batch = (const int*)d_in[2];
    const float* xcb  = (const float*)d_in[3];
    const float* Wl   = (const float*)d_in[4];
    const float* bl   = (const float*)d_in[5];
    const float* Wr   = (const float*)d_in[6];
    const float* br   = (const float*)d_in[7];
    const float* att  = (const float*)d_in[8];
    const float* bias = (const float*)d_in[9];
    float* out = (float*)d_out;

    cudaFuncSetAttribute(k1_main, cudaFuncAttributeMaxDynamicSharedMemorySize, SMEM1);

    k0_xr<<<NR, 256>>>(xcb, Wr, br, att);
    k1_main<<<NCTA, 256, SMEM1>>>(x, Wl, bl, att, batch, bias, out, out_size);
}

// round 12
// speedup vs baseline: 1.0373x; 1.0373x over previous
#include <cuda_runtime.h>
#include <math.h>

// Problem constants (fixed shapes per reference)
#define NN   32768      // nodes
#define KIN  64         // C_in
#define HC   256        // H*C
#define NH   4          // heads
#define NC   64         // C per head
#define NR   16         // ratio
#define NB   32         // graphs
#define NT   512        // NB*NR targets
#define BM   32         // nodes per CTA
#define NCTA (NN/BM)    // 1024
#define NFIN 16         // finalizer CTAs

// smem float offsets; padded total 59392 B so 4 CTAs can't co-reside:
// 3 CTAs/SM -> ~54KB L1D left for Wl caching.
#define OF_XLS 0        // [32][272]
#define OF_EXS 8704     // [32][68]
#define OF_ATT 10880    // [4][68]
#define OF_XS  11152    // [64][32] column-swizzled
#define OF_DXL 13200    // [32][4]
#define SMEM1  59392

typedef unsigned long long ull;

// ---- packed f32x2 helpers (FFMA2 path; only reachable via PTX) ----
#define FMA2(d, a, b, c) asm("fma.rn.f32x2 %0, %1, %2, %3;" : "=l"(d) : "l"(a), "l"(b), "l"(c))
#define ADD2(d, a, b)    asm("add.rn.f32x2 %0, %1, %2;" : "=l"(d) : "l"(a), "l"(b))
#define ABS2(d, a)       asm("and.b64 %0, %1, 0x7FFFFFFF7FFFFFFF;" : "=l"(d) : "l"(a))
#define PACK2(d, lo, hi) asm("mov.b64 %0, {%1, %2};" : "=l"(d) : "r"(lo), "r"(hi))

__device__ __forceinline__ ull pack_dup(float v) {
    ull d; unsigned u = __float_as_uint(v); PACK2(d, u, u); return d;
}
__device__ __forceinline__ float2 as_f2(ull v) {
    float2 r; unsigned lo = (unsigned)v, hi = (unsigned)(v >> 32);
    r.x = __uint_as_float(lo); r.y = __uint_as_float(hi); return r;
}
__device__ __forceinline__ ull as_u64(float lo, float hi) {
    ull d; PACK2(d, __float_as_uint(lo), __float_as_uint(hi)); return d;
}

// ---- scratch (static device globals; no allocation) ----
// g_den / g_num start zero (.bss) and are RE-ZEROED by the finalizer CTAs of
// each run for the next run. g_cnt is a monotone arrival counter (never reset).
__device__ float g_xrL[64 * 64];       // [c>>2][rh][c&3]  (coalesced for logit)
__device__ float g_dxr[64];            // [rh] = sum_c xr*att
__device__ float g_den[NB * 64];       // per (g, rh)
__device__ float g_num[NT * NH * NC];  // [t][h][c]
__device__ unsigned g_cnt;

// ---------------------------------------------------------------------------
// K0: x_r = xcent_base @ W_r + b_r  (interleaved layout) + dxr reduction
// ---------------------------------------------------------------------------
__global__ void __launch_bounds__(256)
k0_xr(const float* __restrict__ xcb, const float* __restrict__ Wr,
      const float* __restrict__ br, const float* __restrict__ att) {
    __shared__ float xc[KIN];
    __shared__ float va[256];
    int r = blockIdx.x;
    int o = threadIdx.x;               // output column of W_r
    if (o < KIN) xc[o] = xcb[r * KIN + o];
    __syncthreads();

    float s[4] = {0.f, 0.f, 0.f, 0.f};
    #pragma unroll
    for (int kb = 0; kb < KIN; kb += 16) {
        float w[16];
        #pragma unroll
        for (int j = 0; j < 16; j++) w[j] = __ldg(Wr + (kb + j) * HC + o);
        #pragma unroll
        for (int j = 0; j < 16; j++) s[j & 3] = fmaf(xc[kb + j], w[j], s[j & 3]);
    }
    int h = o >> 6, c = o & 63;
    int rh = r * 4 + h;
    float val = br[o] + ((s[0] + s[1]) + (s[2] + s[3]));
    g_xrL[((c >> 2) * 64 + rh) * 4 + (c & 3)] = val;
    va[o] = val * att[o];              // att flat [h*64+c] == o
    __syncthreads();
    if (o < 4) {
        float d = 0.f;
        #pragma unroll 8
        for (int j = 0; j < 64; j++) d += va[o * 64 + j];
        g_dxr[r * 4 + o] = d;
    }
}

// ---------------------------------------------------------------------------
// K1 (fused): per 32-node tile, 3 CTAs/SM (smem-padded; ~54KB L1D for Wl)
//   phase1: GEMM x@W_l+b_l; B from GLOBAL in k=4 register chunks (MLP-4);
//           xs column-swizzled (conflict-free STS, broadcast LDS)
//   phase1b: dxl[n][h] = sum_c xl*att  (tiny, 128 threads)
//   phase2: logit = 0.6*(dxl+dxr) + 0.4*sum|z|a; expf; den red.f32
//   phase3: numerator accumulation -> red.v4 to g_num
//   phase4: last 16 CTAs finalize output + re-zero accumulators
// ---------------------------------------------------------------------------
__global__ void __launch_bounds__(256, 3)
k1_main(const float* __restrict__ x, const float* __restrict__ Wl,
        const float* __restrict__ bl, const float* __restrict__ att,
        const int* __restrict__ batch, const float* __restrict__ bias,
        float* __restrict__ out, int out_size) {
    extern __shared__ float sm[];
    float* xls  = sm + OF_XLS;         // [n][h*68+c] stride 272
    float* exs  = sm + OF_EXS;         // [n][h*16+r] stride 68
    float* atts = sm + OF_ATT;         // [h*68+c]
    float* xs   = sm + OF_XS;          // [k][col] stride 32, col=(n+4*(k>>3))&31
    float* dxl  = sm + OF_DXL;         // [n][h]

    int tid = threadIdx.x;
    int nb0 = blockIdx.x * BM;
    int g = batch[nb0];

    // --- fill: x tile to xs[k][(n+4*(k>>3))&31] (conflict-free STS) ---
    {
        int n  = tid >> 3;             // 0..31
        int kq = (tid & 7) * 8;        // k-chunk base
        int m  = kq >> 3;              // chunk index 0..7
        int col = (n + 4 * m) & 31;    // constant per thread; distinct per warp
        float4 v0 = *(const float4*)(x + (nb0 + n) * KIN + kq);
        float4 v1 = *(const float4*)(x + (nb0 + n) * KIN + kq + 4);
        xs[(kq + 0) * 32 + col] = v0.x; xs[(kq + 1) * 32 + col] = v0.y;
        xs[(kq + 2) * 32 + col] = v0.z; xs[(kq + 3) * 32 + col] = v0.w;
        xs[(kq + 4) * 32 + col] = v1.x; xs[(kq + 5) * 32 + col] = v1.y;
        xs[(kq + 6) * 32 + col] = v1.z; xs[(kq + 7) * 32 + col] = v1.w;
    }
    // --- fill: att -> atts ---
    {
        int h = tid >> 6, c = tid & 63;
        atts[h * 68 + c] = att[tid];
    }
    __syncthreads();

    // --- GEMM (packed f32x2): thread (tn 0..3, to 0..63)
    //     nodes tn*8..tn*8+7; cols to*4..to*4+3. B from global, kc=4 chunks
    //     (MLP-4, coalesced 512B/warp). a-loads warp-uniform broadcast. ---
    int to = tid & 63, tn = tid >> 6;

    ull acc2[8][2];      // [node i][col pair]  (32 regs)
    #pragma unroll
    for (int i = 0; i < 8; i++) { acc2[i][0] = 0ull; acc2[i][1] = 0ull; }

    const float4* wp4 = (const float4*)(Wl + to * 4);   // +k*64 float4s per row
    #pragma unroll 2
    for (int kb = 0; kb < 64; kb += 4) {
        ull b2[4][2];                  // 16 regs, MLP=4 LDG.128
        #pragma unroll
        for (int j = 0; j < 4; j++) {
            float4 w = __ldg(wp4 + (kb + j) * 64);
            b2[j][0] = as_u64(w.x, w.y);
            b2[j][1] = as_u64(w.z, w.w);
        }
        #pragma unroll
        for (int j = 0; j < 4; j++) {
            int k = kb + j;
            int m4 = (k >> 3) * 4;
            int c0 = (tn * 8 + m4) & 31;       // swizzled col of node tn*8
            int c1 = (tn * 8 + 4 + m4) & 31;   // swizzled col of node tn*8+4
            float4 a0 = *(const float4*)(xs + k * 32 + c0);   // bcast
            float4 a1 = *(const float4*)(xs + k * 32 + c1);   // bcast
            ull ad[8];
            ad[0] = pack_dup(a0.x); ad[1] = pack_dup(a0.y);
            ad[2] = pack_dup(a0.z); ad[3] = pack_dup(a0.w);
            ad[4] = pack_dup(a1.x); ad[5] = pack_dup(a1.y);
            ad[6] = pack_dup(a1.z); ad[7] = pack_dup(a1.w);
            #pragma unroll
            for (int i = 0; i < 8; i++) {
                FMA2(acc2[i][0], ad[i], b2[j][0], acc2[i][0]);
                FMA2(acc2[i][1], ad[i], b2[j][1], acc2[i][1]);
            }
        }
    }

    // --- epilogue: add bias (packed), store to SMEM xls [n][h*68+c] ---
    {
        int h = to >> 4;               // head of this column quad
        int c = (to & 15) * 4;
        float4 bv = __ldg((const float4*)(bl + to * 4));
        ull blo = as_u64(bv.x, bv.y), bhi = as_u64(bv.z, bv.w);
        #pragma unroll
        for (int i = 0; i < 8; i++) {
            int n = tn * 8 + i;
            ull v0, v1;
            ADD2(v0, acc2[i][0], blo);
            ADD2(v1, acc2[i][1], bhi);
            ulonglong2 st; st.x = v0; st.y = v1;
            *(ulonglong2*)(xls + n * 272 + h * 68 + c) = st;
        }
    }
    __syncthreads();

    // --- phase1b: dxl[n][h] = sum_c xl*att (128 threads, conflict-free) ---
    if (tid < 128) {
        int n = tid >> 2, h = tid & 3;
        ull a2 = 0ull;
        #pragma unroll
        for (int j = 0; j < 16; j++) {
            ulonglong2 xl = *(const ulonglong2*)(xls + n * 272 + h * 68 + j * 4);
            ulonglong2 at = *(const ulonglong2*)(atts + h * 68 + j * 4);
            FMA2(a2, xl.x, at.x, a2);
            FMA2(a2, xl.y, at.y, a2);
        }
        float2 f = as_f2(a2);
        dxl[n * 4 + h] = f.x + f.y;
    }
    __syncthreads();

    // --- logit + exp, q-tiled: s = 0.6*(dxl+dxr) + 0.4*sum|z|a; den folded ---
    {
        int rh = tid & 63;   // r*4+h
        int nl = tid >> 6;   // 0..3
        int hh = rh & 3;
        int rr = rh >> 2;
        float dxr = __ldg(g_dxr + rh);

        ull s2[8];
        #pragma unroll
        for (int i = 0; i < 8; i++) s2[i] = 0ull;

        #pragma unroll
        for (int qt = 0; qt < 4; qt++) {
            ull at2[8], xr2[8];
            #pragma unroll
            for (int j = 0; j < 4; j++) {
                ulonglong2 t = *(const ulonglong2*)(atts + hh * 68 + qt * 16 + j * 4);
                at2[2 * j] = t.x; at2[2 * j + 1] = t.y;
                // coalesced: lanes rh 0..31 -> consecutive 16B
                float4 u = __ldg((const float4*)(g_xrL + ((qt * 4 + j) * 64 + rh) * 4));
                xr2[2 * j] = as_u64(u.x, u.y); xr2[2 * j + 1] = as_u64(u.z, u.w);
            }
            #pragma unroll
            for (int i = 0; i < 8; i++) {
                int n = nl + 4 * i;
                #pragma unroll
                for (int j = 0; j < 4; j++) {
                    ulonglong2 xl = *(const ulonglong2*)(xls + n * 272 + hh * 68 + qt * 16 + j * 4);
                    ull z, az;
                    ADD2(z, xl.x, xr2[2 * j]);
                    ABS2(az, z);
                    FMA2(s2[i], az, at2[2 * j], s2[i]);
                    ADD2(z, xl.y, xr2[2 * j + 1]);
                    ABS2(az, z);
                    FMA2(s2[i], az, at2[2 * j + 1], s2[i]);
                }
            }
        }

        float den_part = 0.f;
        #pragma unroll
        for (int i = 0; i < 8; i++) {
            int n = nl + 4 * i;
            float2 f2v = as_f2(s2[i]);
            float logit = 0.6f * (dxl[n * 4 + hh] + dxr) + 0.4f * (f2v.x + f2v.y);
            // no max subtraction: logits are O(+-10), exp is safe in fp32
            float e = __expf(logit);
            exs[n * 68 + hh * 16 + rr] = e;
            den_part += e;
        }
        asm volatile("red.global.add.f32 [%0], %1;"
                     :: "l"(g_den + g * 64 + rh), "f"(den_part) : "memory");
    }
    __syncthreads();

    // --- numerator accumulation (packed): thread = (rp, h, cq) ---
    {
        int rp = tid >> 6;          // r-quad: r = rp*4..rp*4+3
        int h  = (tid >> 4) & 3;
        int cq = tid & 15;          // c = cq*4..cq*4+3

        ull a2[4][2];
        #pragma unroll
        for (int r = 0; r < 4; r++) { a2[r][0] = 0ull; a2[r][1] = 0ull; }

        #pragma unroll 4
        for (int n = 0; n < BM; n++) {
            float4 e = *(const float4*)(exs + n * 68 + h * 16 + rp * 4);
            ulonglong2 v = *(const ulonglong2*)(xls + n * 272 + h * 68 + cq * 4);
            ull e0 = pack_dup(e.x), e1 = pack_dup(e.y);
            ull e2 = pack_dup(e.z), e3 = pack_dup(e.w);
            FMA2(a2[0][0], e0, v.x, a2[0][0]); FMA2(a2[0][1], e0, v.y, a2[0][1]);
            FMA2(a2[1][0], e1, v.x, a2[1][0]); FMA2(a2[1][1], e1, v.y, a2[1][1]);
            FMA2(a2[2][0], e2, v.x, a2[2][0]); FMA2(a2[2][1], e2, v.y, a2[2][1]);
            FMA2(a2[3][0], e3, v.x, a2[3][0]); FMA2(a2[3][1], e3, v.y, a2[3][1]);
        }
        float* base = g_num + ((g * NR + rp * 4) * NH + h) * NC + cq * 4;
        #pragma unroll
        for (int r = 0; r < 4; r++) {
            float2 lo = as_f2(a2[r][0]), hi = as_f2(a2[r][1]);
            asm volatile("red.global.add.v4.f32 [%0], {%1,%2,%3,%4};"
                         :: "l"(base + r * NH * NC),
                            "f"(lo.x), "f"(lo.y), "f"(hi.x), "f"(hi.y) : "memory");
        }
    }

    // --- phase4: arrival ticket; last NFIN CTAs finalize + re-zero ---
    __shared__ unsigned s_tk;
    __threadfence();                 // release my reds (every thread)
    __syncthreads();
    if (tid == 0) s_tk = atomicAdd(&g_cnt, 1u);
    __syncthreads();
    unsigned tk  = s_tk;
    unsigned pos = tk & (NCTA - 1);  // position within this run (NCTA power of 2)
    if (pos < NCTA - NFIN) return;

    unsigned run_base = tk - pos;
    if (tid == 0) {
        // wrap-safe monotone wait: all NCTA CTAs of this run have arrived
        while (*((volatile unsigned*)&g_cnt) - run_base < NCTA) { }
    }
    __syncthreads();
    __threadfence();                 // acquire: all reds visible

    int slice = (int)(pos - (NCTA - NFIN));   // 0..15
    int t0 = slice * (NT / NFIN);             // 32 t's per slice

    // reciprocal of den for my t-range: 2 graphs x 64 rh = 128 values -> smem
    float* rden = sm;                         // reuse smem
    if (tid < 128) {
        int gg = 2 * slice + (tid >> 6);
        rden[tid] = 1.0f / g_den[gg * 64 + (tid & 63)];
    }
    __syncthreads();

    // outputs: 32 t x 64 c = 2048 values
    for (int i = tid; i < (NT / NFIN) * NC; i += 256) {
        int t = t0 + (i >> 6), c = i & 63;
        int lg = (t >> 4) - 2 * slice;        // 0 or 1
        int r  = t & 15;
        float s = 0.f;
        #pragma unroll
        for (int h = 0; h < NH; h++)
            s += g_num[(t * NH + h) * NC + c] * rden[lg * 64 + r * 4 + h];
        out[t * NC + c] = 0.25f * s + bias[c];
    }
    // batchcent tail
    {
        int j = t0 + tid;                     // 32 entries per slice
        if (tid < NT / NFIN && NT * NC + j < out_size)
            out[NT * NC + j] = (float)(j >> 4);
    }
    __syncthreads();                          // reads done before re-zero

    // re-zero my disjoint slices for the next run
    {
        float4 z4 = {0.f, 0.f, 0.f, 0.f};
        float* nb = g_num + t0 * NH * NC;     // 32*256 = 8192 floats
        for (int i = tid * 4; i < (NT / NFIN) * NH * NC; i += 1024)
            *(float4*)(nb + i) = z4;
        if (tid < 32)
            *(float4*)(g_den + slice * 128 + tid * 4) = z4;
    }
}

// ---------------------------------------------------------------------------
extern "C" void kernel_launch(void* const* d_in, const int* in_sizes, int n_in,
                              void* d_out, int out_size) {
    const float* x    = (const float*)d_in[0];
    // d_in[1] = edge_index (unused by forward)
    const int*   batch = (const int*)d_in[2];
    const float* xcb  = (const float*)d_in[3];
    const float* Wl   = (const float*)d_in[4];
    const float* bl   = (const float*)d_in[5];
    const float* Wr   = (const float*)d_in[6];
    const float* br   = (const float*)d_in[7];
    const float* att  = (const float*)d_in[8];
    const float* bias = (const float*)d_in[9];
    float* out = (float*)d_out;

    cudaFuncSetAttribute(k1_main, cudaFuncAttributeMaxDynamicSharedMemorySize, SMEM1);

    k0_xr<<<NR, 256>>>(xcb, Wr, br, att);
    k1_main<<<NCTA, 256, SMEM1>>>(x, Wl, bl, att, batch, bias, out, out_size);
}